// round 6
// baseline (speedup 1.0000x reference)
#include <cuda_runtime.h>
#include <cstdint>

#define HIDDEN   2048
#define INTER    1408
#define GU_ROWS  (2 * INTER)   // 2816
#define TOPK     6
#define NEXPERTS 60

// Scratch (allocation-free rule: __device__ globals)
__device__ __align__(16) float g_y[TOPK * GU_ROWS];     // gate_up GEMV results
__device__ __align__(16) float g_inter[TOPK * INTER];   // silu(gate)*up

// topk_idx may be int32 or int64 depending on JAX x64 config.
// int64 little-endian pattern over first 6 words: [v0,0,v1,0,v2,0], v<60.
__device__ __forceinline__ int load_expert_idx(const void* p, int k) {
    const int* w = (const int*)p;
    bool is64 = (w[1] == 0) & (w[3] == 0) & (w[5] == 0) &
                ((unsigned)w[0] < (unsigned)NEXPERTS) &
                ((unsigned)w[2] < (unsigned)NEXPERTS) &
                ((unsigned)w[4] < (unsigned)NEXPERTS);
    if (is64) return (int)((const long long*)p)[k];
    return w[k];
}

// ---------------------------------------------------------------------------
// Phase 1: y[k][j] = dot(gate_up_all[e_k][j][:], x)   (6*2816 rows, warp/row)
// ---------------------------------------------------------------------------
__global__ __launch_bounds__(256) void gu_gemv_kernel(
    const float* __restrict__ x,
    const void*  __restrict__ idx,
    const float* __restrict__ gu)
{
    int warp = (blockIdx.x * blockDim.x + threadIdx.x) >> 5;
    int lane = threadIdx.x & 31;
    if (warp >= TOPK * GU_ROWS) return;

    int k = warp / GU_ROWS;
    int j = warp - k * GU_ROWS;
    int e = load_expert_idx(idx, k);

    const float4* __restrict__ wrow =
        (const float4*)(gu + ((size_t)e * GU_ROWS + j) * HIDDEN);
    const float4* __restrict__ xv = (const float4*)x;

    float acc = 0.f;
#pragma unroll
    for (int i = 0; i < HIDDEN / 4 / 32; i++) {   // 16 iters, fully unrolled
        float4 a = wrow[lane + 32 * i];
        float4 b = xv[lane + 32 * i];             // L1-hot (8 KB vector)
        acc += a.x * b.x + a.y * b.y + a.z * b.z + a.w * b.w;
    }
#pragma unroll
    for (int s = 16; s; s >>= 1) acc += __shfl_xor_sync(0xFFFFFFFFu, acc, s);

    if (lane == 0) g_y[warp] = acc;
}

// ---------------------------------------------------------------------------
// Phase 1.5: inter[k][i] = silu(y[k][i]) * y[k][1408+i]
// ---------------------------------------------------------------------------
__global__ void silu_mul_kernel()
{
    int t = blockIdx.x * blockDim.x + threadIdx.x;
    if (t >= TOPK * INTER) return;
    int k = t / INTER;
    int i = t - k * INTER;
    float g = g_y[k * GU_ROWS + i];
    float u = g_y[k * GU_ROWS + INTER + i];
    g_inter[t] = (g / (1.f + __expf(-g))) * u;
}

// ---------------------------------------------------------------------------
// Phase 2: out[h] = sum_k w_k * dot(down_all[e_k][h][:], inter[k][:])
// block = one h, 6 warps (one per expert), smem reduce. Deterministic.
// ---------------------------------------------------------------------------
__global__ __launch_bounds__(TOPK * 32) void down_gemv_kernel(
    const void*  __restrict__ idx,
    const float* __restrict__ wts,
    const float* __restrict__ down,
    float*       __restrict__ out)
{
    int h    = blockIdx.x;
    int k    = threadIdx.x >> 5;
    int lane = threadIdx.x & 31;
    int e    = load_expert_idx(idx, k);

    const float4* __restrict__ wrow =
        (const float4*)(down + ((size_t)e * HIDDEN + h) * INTER);
    const float4* __restrict__ iv = (const float4*)(g_inter + k * INTER);

    float acc = 0.f;
#pragma unroll
    for (int i = 0; i < INTER / 4 / 32; i++) {    // 11 iters, fully unrolled
        float4 a = wrow[lane + 32 * i];
        float4 b = iv[lane + 32 * i];             // L2-resident (34 KB)
        acc += a.x * b.x + a.y * b.y + a.z * b.z + a.w * b.w;
    }
#pragma unroll
    for (int s = 16; s; s >>= 1) acc += __shfl_xor_sync(0xFFFFFFFFu, acc, s);

    __shared__ float part[TOPK];
    if (lane == 0) part[k] = acc * wts[k];
    __syncthreads();

    if (threadIdx.x == 0) {
        float s = 0.f;
#pragma unroll
        for (int i = 0; i < TOPK; i++) s += part[i];
        out[h] = s;
    }
}

// ---------------------------------------------------------------------------
// Inputs (metadata order): x_bc1t[2048] f32, topk_idx[6] i32/i64,
// topk_weights[6] f32, gate_up_all[60*2816*2048] f32, down_all[60*2048*1408] f32
// Output: [2048] f32
// ---------------------------------------------------------------------------
extern "C" void kernel_launch(void* const* d_in, const int* in_sizes, int n_in,
                              void* d_out, int out_size)
{
    const float* x    = (const float*)d_in[0];
    const void*  idx  = d_in[1];
    const float* wts  = (const float*)d_in[2];
    const float* gu   = (const float*)d_in[3];
    const float* down = (const float*)d_in[4];
    float*       out  = (float*)d_out;

    const int total_threads_p1 = TOPK * GU_ROWS * 32;       // 16896 warps
    gu_gemv_kernel<<<(total_threads_p1 + 255) / 256, 256>>>(x, idx, gu);

    silu_mul_kernel<<<(TOPK * INTER + 255) / 256, 256>>>();

    down_gemv_kernel<<<HIDDEN, TOPK * 32>>>(idx, wts, down, out);
}

// round 8
// speedup vs baseline: 1.0293x; 1.0293x over previous
#include <cuda_runtime.h>
#include <cstdint>

#define HIDDEN   2048
#define INTER    1408
#define GU_ROWS  (2 * INTER)   // 2816
#define TOPK     6
#define NEXPERTS 60

// Scratch (allocation-free rule: __device__ globals)
__device__ __align__(16) float g_y[TOPK * GU_ROWS];     // gate_up GEMV results
__device__ __align__(16) float g_inter[TOPK * INTER];   // silu(gate)*up

// topk_idx may be int32 or int64 depending on JAX x64 config.
// int64 little-endian pattern over first 6 words: [v0,0,v1,0,v2,0], v<60.
__device__ __forceinline__ int load_expert_idx(const void* p, int k) {
    const int* w = (const int*)p;
    bool is64 = (w[1] == 0) & (w[3] == 0) & (w[5] == 0) &
                ((unsigned)w[0] < (unsigned)NEXPERTS) &
                ((unsigned)w[2] < (unsigned)NEXPERTS) &
                ((unsigned)w[4] < (unsigned)NEXPERTS);
    if (is64) return (int)((const long long*)p)[k];
    return w[k];
}

// ---------------------------------------------------------------------------
// Phase 1: y[k][j] = dot(gate_up_all[e_k][j][:], x)   (6*2816 rows, warp/row)
// ---------------------------------------------------------------------------
__global__ __launch_bounds__(256) void gu_gemv_kernel(
    const float* __restrict__ x,
    const void*  __restrict__ idx,
    const float* __restrict__ gu)
{
    int warp = (blockIdx.x * blockDim.x + threadIdx.x) >> 5;
    int lane = threadIdx.x & 31;
    if (warp >= TOPK * GU_ROWS) return;

    int k = warp / GU_ROWS;
    int j = warp - k * GU_ROWS;
    int e = load_expert_idx(idx, k);

    const float4* __restrict__ wrow =
        (const float4*)(gu + ((size_t)e * GU_ROWS + j) * HIDDEN);
    const float4* __restrict__ xv = (const float4*)x;

    float acc = 0.f;
#pragma unroll
    for (int i = 0; i < HIDDEN / 4 / 32; i++) {   // 16 iters, fully unrolled
        float4 a = wrow[lane + 32 * i];
        float4 b = xv[lane + 32 * i];             // L1-hot (8 KB vector)
        acc += a.x * b.x + a.y * b.y + a.z * b.z + a.w * b.w;
    }
#pragma unroll
    for (int s = 16; s; s >>= 1) acc += __shfl_xor_sync(0xFFFFFFFFu, acc, s);

    if (lane == 0) g_y[warp] = acc;
}

// ---------------------------------------------------------------------------
// Phase 1.5: inter[k][i] = silu(y[k][i]) * y[k][1408+i]
// ---------------------------------------------------------------------------
__global__ void silu_mul_kernel()
{
    int t = blockIdx.x * blockDim.x + threadIdx.x;
    if (t >= TOPK * INTER) return;
    int k = t / INTER;
    int i = t - k * INTER;
    float g = g_y[k * GU_ROWS + i];
    float u = g_y[k * GU_ROWS + INTER + i];
    g_inter[t] = (g / (1.f + __expf(-g))) * u;
}

// ---------------------------------------------------------------------------
// Phase 2: out[h] = sum_k w_k * dot(down_all[e_k][h][:], inter[k][:])
// block = one h, 6 warps (one per expert), smem reduce. Deterministic.
// ---------------------------------------------------------------------------
__global__ __launch_bounds__(TOPK * 32) void down_gemv_kernel(
    const void*  __restrict__ idx,
    const float* __restrict__ wts,
    const float* __restrict__ down,
    float*       __restrict__ out)
{
    int h    = blockIdx.x;
    int k    = threadIdx.x >> 5;
    int lane = threadIdx.x & 31;
    int e    = load_expert_idx(idx, k);

    const float4* __restrict__ wrow =
        (const float4*)(down + ((size_t)e * HIDDEN + h) * INTER);
    const float4* __restrict__ iv = (const float4*)(g_inter + k * INTER);

    float acc = 0.f;
#pragma unroll
    for (int i = 0; i < INTER / 4 / 32; i++) {    // 11 iters, fully unrolled
        float4 a = wrow[lane + 32 * i];
        float4 b = iv[lane + 32 * i];             // L2-resident (34 KB)
        acc += a.x * b.x + a.y * b.y + a.z * b.z + a.w * b.w;
    }
#pragma unroll
    for (int s = 16; s; s >>= 1) acc += __shfl_xor_sync(0xFFFFFFFFu, acc, s);

    __shared__ float part[TOPK];
    if (lane == 0) part[k] = acc * wts[k];
    __syncthreads();

    if (threadIdx.x == 0) {
        float s = 0.f;
#pragma unroll
        for (int i = 0; i < TOPK; i++) s += part[i];
        out[h] = s;
    }
}

// ---------------------------------------------------------------------------
// Inputs (metadata order): x_bc1t[2048] f32, topk_idx[6] i32/i64,
// topk_weights[6] f32, gate_up_all[60*2816*2048] f32, down_all[60*2048*1408] f32
// Output: [2048] f32
// ---------------------------------------------------------------------------
extern "C" void kernel_launch(void* const* d_in, const int* in_sizes, int n_in,
                              void* d_out, int out_size)
{
    const float* x    = (const float*)d_in[0];
    const void*  idx  = d_in[1];
    const float* wts  = (const float*)d_in[2];
    const float* gu   = (const float*)d_in[3];
    const float* down = (const float*)d_in[4];
    float*       out  = (float*)d_out;

    const int total_threads_p1 = TOPK * GU_ROWS * 32;       // 16896 warps
    gu_gemv_kernel<<<(total_threads_p1 + 255) / 256, 256>>>(x, idx, gu);

    silu_mul_kernel<<<(TOPK * INTER + 255) / 256, 256>>>();

    down_gemv_kernel<<<HIDDEN, TOPK * 32>>>(idx, wts, down, out);
}